// round 5
// baseline (speedup 1.0000x reference)
#include <cuda_runtime.h>
#include <cstdint>

// NCutsLoss, fused single kernel, smem-staged weight.
//   acc(b,k,h,w)   = sum_{m,n} padded[b,k,h+m,w+n] * weight[b,0,h,w,m,n]
//   assocA[b,k]    = sum_{h,w} acc * seg
//   assocV[b,k]    = sum_{h,w} sum_weight * seg
//   out[b]         = 8.0 - sum_k assocA/assocV
// B=16, K=8, H=W=128, WIN=9, padded 136x136.

#define BB   16
#define KK   8
#define HH   128
#define WW   128
#define WIN  9
#define WQ   (WIN * WIN)      // 81
#define PH   (HH + WIN - 1)   // 136
#define PW   (WW + WIN - 1)   // 136

#define TH   16               // h-rows per block
#define PROWS (TH + WIN - 1)  // 24 padded rows
#define CHUNKP 3268           // padded k-plane stride (24*136=3264 -> +4, ≡4 mod 32)

#define WCH  16               // w-chunk width
#define NCH  (WW / WCH)       // 8 chunks
#define ROWF (WCH * WQ)       // 1296 floats of weight per (row, chunk)
#define ROWF4 (ROWF / 4)      // 324 float4

#define PAD_FLOATS (KK * CHUNKP)            // 26144
#define WBUF_FLOATS (TH * ROWF)             // 20736
#define SMEM_FLOATS (PAD_FLOATS + WBUF_FLOATS)
#define SMEM_BYTES  (SMEM_FLOATS * 4)       // 187,520 B

#define NTILES (HH / TH)      // 8
#define NBLOCKS (BB * NTILES) // 128

__device__ float    g_part[BB * NTILES * 16];
__device__ unsigned g_ctr = 0;

__global__ __launch_bounds__(512, 1)
void ncuts_fused_kernel(const float* __restrict__ seg,
                        const float* __restrict__ pad,
                        const float* __restrict__ wgt,
                        const float* __restrict__ sw,
                        float* __restrict__ out)
{
    extern __shared__ float smem[];
    float* padsm = smem;                    // [k][3268] padded stride
    float* wbuf  = smem + PAD_FLOATS;       // [16 rows][1296] verbatim weight chunk

    const int b   = blockIdx.y;
    const int h0  = blockIdx.x * TH;
    const int tid = threadIdx.x;            // 0..511 (1-D block)
    const int lane = tid & 31;
    const int ty   = tid >> 5;              // warp id = h-row 0..15
    const int k    = lane & 7;              // k-plane per thread
    const int wq   = lane >> 3;             // w-quad within chunk (0..3)

    // ---- Fill padded-seg tile (contiguous rows, padded k-stride) ----
    #pragma unroll
    for (int kk = 0; kk < KK; ++kk) {
        const float4* src = reinterpret_cast<const float4*>(
            pad + ((size_t)(b * KK + kk) * PH + h0) * PW);
        float4* dst = reinterpret_cast<float4*>(padsm + kk * CHUNKP);
        for (int i = tid; i < (PROWS * PW) / 4; i += 512)
            dst[i] = src[i];
    }

    // Weight row base for this warp's h-row (w=0); rows are 16B-aligned.
    const float* wrowbase = wgt + (((size_t)b * HH + h0 + ty) * WW) * WQ;

    // Prefetch chunk 0 into registers (dense, coalesced: lanes adjacent f4).
    float4 wreg[11];
    {
        const float4* s = reinterpret_cast<const float4*>(wrowbase);
        #pragma unroll
        for (int j = 0; j < 11; ++j) {
            int idx = j * 32 + lane;
            if (idx < ROWF4) wreg[j] = s[idx];
        }
    }

    float vA = 0.0f, vV = 0.0f;

    #pragma unroll 1
    for (int c = 0; c < NCH; ++c) {
        // ---- Store staged chunk to smem (dense STS, conflict-free) ----
        {
            float4* d = reinterpret_cast<float4*>(wbuf + ty * ROWF);
            #pragma unroll
            for (int j = 0; j < 11; ++j) {
                int idx = j * 32 + lane;
                if (idx < ROWF4) d[idx] = wreg[j];
            }
        }
        __syncthreads();   // wbuf ready (and pad fill, on c==0)

        // Prefetch next chunk into registers (in flight during compute).
        if (c + 1 < NCH) {
            const float4* s = reinterpret_cast<const float4*>(
                wrowbase + (size_t)(c + 1) * ROWF);
            #pragma unroll
            for (int j = 0; j < 11; ++j) {
                int idx = j * 32 + lane;
                if (idx < ROWF4) wreg[j] = s[idx];
            }
        }

        const int wloc = c * WCH + wq * 4;  // first of this thread's 4 outputs

        // Prefetch seg / sum_weight for the fold (hide under FMAs).
        float4 segv = *reinterpret_cast<const float4*>(
            seg + (((size_t)(b * KK + k) * HH + h0 + ty) * WW + wloc));
        float4 swv  = *reinterpret_cast<const float4*>(
            sw  + (((size_t)b * HH + h0 + ty) * WW + wloc));

        // ---- Windowed accumulation from smem ----
        // slice-quad: 4 packed 81-float slices, base 16B-aligned.
        const float* sq    = wbuf + ty * ROWF + (wq * 4) * WQ;
        const float* prow0 = padsm + k * CHUNKP + ty * PW + wloc;

        float acc[4] = {0.0f, 0.0f, 0.0f, 0.0f};
        float4 carry[4];
        #pragma unroll
        for (int m = 0; m < WIN; ++m) {
            const int off = m & 3;          // compile-time per unrolled m
            float t[4][12];
            #pragma unroll
            for (int p = 0; p < 4; ++p) {
                const float* ps = sq + p * WQ;
                float4 a, bq, cc;
                if (m == 0 || m == 4) {
                    const int base = (m == 0) ? 0 : 36;
                    a  = *reinterpret_cast<const float4*>(ps + base);
                    bq = *reinterpret_cast<const float4*>(ps + base + 4);
                    cc = *reinterpret_cast<const float4*>(ps + base + 8);
                } else if (m == 8) {
                    a  = *reinterpret_cast<const float4*>(ps + 72);
                    bq = *reinterpret_cast<const float4*>(ps + 76);
                    cc = make_float4(ps[80], 0.0f, 0.0f, 0.0f);
                } else {
                    const int f = ((m <= 3) ? (2 * m + 1) : (2 * m + 2)) * 4;
                    a  = carry[p];
                    bq = *reinterpret_cast<const float4*>(ps + f);
                    cc = *reinterpret_cast<const float4*>(ps + f + 4);
                }
                t[p][0] = a.x;  t[p][1] = a.y;  t[p][2]  = a.z;  t[p][3]  = a.w;
                t[p][4] = bq.x; t[p][5] = bq.y; t[p][6]  = bq.z; t[p][7]  = bq.w;
                t[p][8] = cc.x; t[p][9] = cc.y; t[p][10] = cc.z; t[p][11] = cc.w;
                carry[p] = cc;
            }

            const float* rk = prow0 + m * PW;
            float4 v0 = *reinterpret_cast<const float4*>(rk);
            float4 v1 = *reinterpret_cast<const float4*>(rk + 4);
            float4 v2 = *reinterpret_cast<const float4*>(rk + 8);
            float vals[12] = { v0.x, v0.y, v0.z, v0.w,
                               v1.x, v1.y, v1.z, v1.w,
                               v2.x, v2.y, v2.z, v2.w };
            #pragma unroll
            for (int n = 0; n < WIN; ++n) {
                #pragma unroll
                for (int p = 0; p < 4; ++p)
                    acc[p] = fmaf(vals[n + p], t[p][off + n], acc[p]);
            }
        }

        // ---- Fold with seg / sum_weight ----
        vA = fmaf(acc[0], segv.x, vA);  vA = fmaf(acc[1], segv.y, vA);
        vA = fmaf(acc[2], segv.z, vA);  vA = fmaf(acc[3], segv.w, vA);
        vV = fmaf(swv.x, segv.x, vV);   vV = fmaf(swv.y, segv.y, vV);
        vV = fmaf(swv.z, segv.z, vV);   vV = fmaf(swv.w, segv.w, vV);

        __syncthreads();   // done reading wbuf before next overwrite
    }

    // ---- Reduce over wq (lanes sharing k are 8 apart) ----
    vA += __shfl_xor_sync(0xFFFFFFFFu, vA, 8);
    vA += __shfl_xor_sync(0xFFFFFFFFu, vA, 16);
    vV += __shfl_xor_sync(0xFFFFFFFFu, vV, 8);
    vV += __shfl_xor_sync(0xFFFFFFFFu, vV, 16);

    __shared__ float sred[16][16];   // [warp=h][0..7 A_k, 8..15 V_k]
    if (lane < 8) {
        sred[ty][lane]     = vA;
        sred[ty][8 + lane] = vV;
    }
    __syncthreads();
    if (tid < 16) {
        float s = 0.0f;
        #pragma unroll
        for (int wrp = 0; wrp < 16; ++wrp)
            s += sred[wrp][tid];
        g_part[(b * NTILES + blockIdx.x) * 16 + tid] = s;
        __threadfence();             // publish partials
    }
    __syncthreads();

    // ---- Last-block finalize (deterministic fixed-order sums) ----
    __shared__ unsigned s_last;
    __shared__ float fin[BB * 16];
    if (tid == 0) {
        unsigned old = atomicAdd(&g_ctr, 1u);
        s_last = (old == NBLOCKS - 1) ? 1u : 0u;
    }
    __syncthreads();
    if (s_last) {
        __threadfence();
        if (tid < BB * 16) {
            const int bb = tid >> 4, slot = tid & 15;
            float s = 0.0f;
            #pragma unroll
            for (int ht = 0; ht < NTILES; ++ht)
                s += g_part[(bb * NTILES + ht) * 16 + slot];
            fin[tid] = s;
        }
        __syncthreads();
        if (tid < BB) {
            float assoc = 0.0f;
            #pragma unroll
            for (int kk = 0; kk < KK; ++kk)
                assoc += fin[tid * 16 + kk] / fin[tid * 16 + 8 + kk];
            out[tid] = 8.0f - assoc;
        }
        if (tid == 0) g_ctr = 0;     // reset for next graph replay
    }
}

extern "C" void kernel_launch(void* const* d_in, const int* in_sizes, int n_in,
                              void* d_out, int out_size)
{
    const float *seg = nullptr, *pad = nullptr, *wgt = nullptr, *sw = nullptr;
    for (int i = 0; i < n_in; ++i) {
        int sz = in_sizes[i];
        if      (sz == BB * KK * HH * WW)        seg = (const float*)d_in[i];
        else if (sz == BB * KK * PH * PW)        pad = (const float*)d_in[i];
        else if (sz == BB * HH * WW * WQ)        wgt = (const float*)d_in[i];
        else if (sz == BB * HH * WW)             sw  = (const float*)d_in[i];
    }
    float* out = (float*)d_out;

    cudaFuncSetAttribute(ncuts_fused_kernel,
                         cudaFuncAttributeMaxDynamicSharedMemorySize, SMEM_BYTES);

    dim3 grid(NTILES, BB);     // 128 blocks, one wave
    ncuts_fused_kernel<<<grid, 512, SMEM_BYTES>>>(seg, pad, wgt, sw, out);
}

// round 6
// speedup vs baseline: 1.0976x; 1.0976x over previous
#include <cuda_runtime.h>
#include <cstdint>

// NCutsLoss, fused single kernel, cp.async-staged weight, per-warp pipeline.
//   acc(b,k,h,w)   = sum_{m,n} padded[b,k,h+m,w+n] * weight[b,0,h,w,m,n]
//   assocA[b,k]    = sum_{h,w} acc * seg
//   assocV[b,k]    = sum_{h,w} sum_weight * seg
//   out[b]         = 8.0 - sum_k assocA/assocV
// B=16, K=8, H=W=128, WIN=9, padded 136x136.

#define BB   16
#define KK   8
#define HH   128
#define WW   128
#define WIN  9
#define WQ   (WIN * WIN)      // 81
#define PH   (HH + WIN - 1)   // 136
#define PW   (WW + WIN - 1)   // 136

#define TH   16               // h-rows per block
#define PROWS (TH + WIN - 1)  // 24 padded rows
#define CHUNKP 3268           // padded k-plane stride (3264+4, ≡4 mod 32 banks)

#define WCH  16               // w-chunk width (pixels)
#define NCH  (WW / WCH)       // 8 chunks
#define ROWF (WCH * WQ)       // 1296 weight floats per (row, chunk)
#define ROWF4 (ROWF / 4)      // 324 float4

#define PAD_FLOATS  (KK * CHUNKP)           // 26144
#define WBUF_FLOATS (TH * ROWF)             // 20736 (per-warp-private rows)
#define SMEM_FLOATS (PAD_FLOATS + WBUF_FLOATS)
#define SMEM_BYTES  (SMEM_FLOATS * 4)       // 187,520 B

#define NTILES (HH / TH)      // 8
#define NBLOCKS (BB * NTILES) // 128

__device__ float    g_part[BB * NTILES * 16];
__device__ unsigned g_ctr = 0;

__device__ __forceinline__ void cpa16(uint32_t dst_smem, const void* src) {
    asm volatile("cp.async.ca.shared.global [%0], [%1], 16;\n"
                 :: "r"(dst_smem), "l"(src));
}
__device__ __forceinline__ void cpa_commit() {
    asm volatile("cp.async.commit_group;\n");
}
__device__ __forceinline__ void cpa_wait0() {
    asm volatile("cp.async.wait_group 0;\n");
}

__global__ __launch_bounds__(512, 1)
void ncuts_fused_kernel(const float* __restrict__ seg,
                        const float* __restrict__ pad,
                        const float* __restrict__ wgt,
                        const float* __restrict__ sw,
                        float* __restrict__ out)
{
    extern __shared__ float smem[];
    float* padsm = smem;                    // [k][3268]
    float* wbuf  = smem + PAD_FLOATS;       // [16 rows][1296], row = warp-private

    const int b    = blockIdx.y;
    const int h0   = blockIdx.x * TH;
    const int tid  = threadIdx.x;           // 0..511
    const int lane = tid & 31;
    const int ty   = tid >> 5;              // warp id = h-row
    const int k    = lane & 7;              // k-plane per thread
    const int wq   = lane >> 3;             // w-quad within chunk (0..3)

    // Weight row base for this warp's h-row; 16B-aligned (row = 41472 B).
    const float* wrowbase = wgt + (((size_t)b * HH + h0 + ty) * WW) * WQ;
    float* myrow = wbuf + ty * ROWF;
    const uint32_t myrow_s = (uint32_t)__cvta_generic_to_shared(myrow);

    // ---- Issue async copy of weight chunk 0 (warp-private target) ----
    #pragma unroll
    for (int j = 0; j < 11; ++j) {
        int idx = j * 32 + lane;
        if (idx < ROWF4)
            cpa16(myrow_s + idx * 16, wrowbase + idx * 4);
    }
    cpa_commit();

    // ---- Fill padded-seg tile (block-cooperative, coalesced float4) ----
    #pragma unroll
    for (int kk = 0; kk < KK; ++kk) {
        const float4* src = reinterpret_cast<const float4*>(
            pad + ((size_t)(b * KK + kk) * PH + h0) * PW);
        float4* dst = reinterpret_cast<float4*>(padsm + kk * CHUNKP);
        for (int i = tid; i < (PROWS * PW) / 4; i += 512)
            dst[i] = src[i];
    }
    __syncthreads();   // pad tile ready for all warps (only block barrier)

    float vA = 0.0f, vV = 0.0f;

    #pragma unroll 1
    for (int c = 0; c < NCH; ++c) {
        cpa_wait0();       // this warp's chunk-c copies complete
        __syncwarp();

        const int wloc = c * WCH + wq * 4;   // first of this thread's 4 pixels

        // seg / sum_weight for the fold (LDG, hidden under FMAs)
        float4 segv = *reinterpret_cast<const float4*>(
            seg + (((size_t)(b * KK + k) * HH + h0 + ty) * WW + wloc));
        float4 swv  = *reinterpret_cast<const float4*>(
            sw  + (((size_t)b * HH + h0 + ty) * WW + wloc));

        const float* sq    = myrow + (wq * 4) * WQ;          // 4 packed slices
        const float* prow0 = padsm + k * CHUNKP + ty * PW + wloc;

        float acc[4] = {0.0f, 0.0f, 0.0f, 0.0f};
        float4 carry[4];
        #pragma unroll
        for (int m = 0; m < WIN; ++m) {
            const int off = m & 3;           // compile-time per unrolled m

            // pad window row (LDS.128, conflict-free)
            const float* rk = prow0 + m * PW;
            float4 v0 = *reinterpret_cast<const float4*>(rk);
            float4 v1 = *reinterpret_cast<const float4*>(rk + 4);
            float4 v2 = *reinterpret_cast<const float4*>(rk + 8);
            float vals[12] = { v0.x, v0.y, v0.z, v0.w,
                               v1.x, v1.y, v1.z, v1.w,
                               v2.x, v2.y, v2.z, v2.w };

            #pragma unroll
            for (int p = 0; p < 4; ++p) {
                const float* ps = sq + p * WQ;
                float4 a, bq, cc;
                if (m == 0 || m == 4) {
                    const int base = (m == 0) ? 0 : 36;
                    a  = *reinterpret_cast<const float4*>(ps + base);
                    bq = *reinterpret_cast<const float4*>(ps + base + 4);
                    cc = *reinterpret_cast<const float4*>(ps + base + 8);
                } else if (m == 8) {
                    a  = *reinterpret_cast<const float4*>(ps + 72);
                    bq = *reinterpret_cast<const float4*>(ps + 76);
                    cc = make_float4(ps[80], 0.0f, 0.0f, 0.0f);
                } else {
                    const int f = ((m <= 3) ? (2 * m + 1) : (2 * m + 2)) * 4;
                    a  = carry[p];
                    bq = *reinterpret_cast<const float4*>(ps + f);
                    cc = *reinterpret_cast<const float4*>(ps + f + 4);
                }
                float tp[12] = { a.x,  a.y,  a.z,  a.w,
                                 bq.x, bq.y, bq.z, bq.w,
                                 cc.x, cc.y, cc.z, cc.w };
                carry[p] = cc;
                #pragma unroll
                for (int n = 0; n < WIN; ++n)
                    acc[p] = fmaf(vals[n + p], tp[off + n], acc[p]);
            }
        }

        // ---- Fold with seg / sum_weight ----
        vA = fmaf(acc[0], segv.x, vA);  vA = fmaf(acc[1], segv.y, vA);
        vA = fmaf(acc[2], segv.z, vA);  vA = fmaf(acc[3], segv.w, vA);
        vV = fmaf(swv.x, segv.x, vV);   vV = fmaf(swv.y, segv.y, vV);
        vV = fmaf(swv.z, segv.z, vV);   vV = fmaf(swv.w, segv.w, vV);

        __syncwarp();      // all lanes done reading myrow for chunk c

        // ---- Issue async copy of next chunk (warp-private; overlaps with
        //      other warps' compute and this warp's reduction tail) ----
        if (c + 1 < NCH) {
            const float* src = wrowbase + (size_t)(c + 1) * ROWF;
            #pragma unroll
            for (int j = 0; j < 11; ++j) {
                int idx = j * 32 + lane;
                if (idx < ROWF4)
                    cpa16(myrow_s + idx * 16, src + idx * 4);
            }
            cpa_commit();
        }
    }

    // ---- Reduce over wq (lanes sharing k are 8 apart) ----
    vA += __shfl_xor_sync(0xFFFFFFFFu, vA, 8);
    vA += __shfl_xor_sync(0xFFFFFFFFu, vA, 16);
    vV += __shfl_xor_sync(0xFFFFFFFFu, vV, 8);
    vV += __shfl_xor_sync(0xFFFFFFFFu, vV, 16);

    __shared__ float sred[16][16];   // [warp=h][0..7 A_k, 8..15 V_k]
    if (lane < 8) {
        sred[ty][lane]     = vA;
        sred[ty][8 + lane] = vV;
    }
    __syncthreads();
    if (tid < 16) {
        float s = 0.0f;
        #pragma unroll
        for (int wrp = 0; wrp < 16; ++wrp)
            s += sred[wrp][tid];
        g_part[(b * NTILES + blockIdx.x) * 16 + tid] = s;
        __threadfence();             // publish partials
    }
    __syncthreads();

    // ---- Last-block finalize (deterministic fixed-order sums) ----
    __shared__ unsigned s_last;
    __shared__ float fin[BB * 16];
    if (tid == 0) {
        unsigned old = atomicAdd(&g_ctr, 1u);
        s_last = (old == NBLOCKS - 1) ? 1u : 0u;
    }
    __syncthreads();
    if (s_last) {
        __threadfence();
        if (tid < BB * 16) {
            const int bb = tid >> 4, slot = tid & 15;
            float s = 0.0f;
            #pragma unroll
            for (int ht = 0; ht < NTILES; ++ht)
                s += g_part[(bb * NTILES + ht) * 16 + slot];
            fin[tid] = s;
        }
        __syncthreads();
        if (tid < BB) {
            float assoc = 0.0f;
            #pragma unroll
            for (int kk = 0; kk < KK; ++kk)
                assoc += fin[tid * 16 + kk] / fin[tid * 16 + 8 + kk];
            out[tid] = 8.0f - assoc;
        }
        if (tid == 0) g_ctr = 0;     // reset for next graph replay
    }
}

extern "C" void kernel_launch(void* const* d_in, const int* in_sizes, int n_in,
                              void* d_out, int out_size)
{
    const float *seg = nullptr, *pad = nullptr, *wgt = nullptr, *sw = nullptr;
    for (int i = 0; i < n_in; ++i) {
        int sz = in_sizes[i];
        if      (sz == BB * KK * HH * WW)        seg = (const float*)d_in[i];
        else if (sz == BB * KK * PH * PW)        pad = (const float*)d_in[i];
        else if (sz == BB * HH * WW * WQ)        wgt = (const float*)d_in[i];
        else if (sz == BB * HH * WW)             sw  = (const float*)d_in[i];
    }
    float* out = (float*)d_out;

    cudaFuncSetAttribute(ncuts_fused_kernel,
                         cudaFuncAttributeMaxDynamicSharedMemorySize, SMEM_BYTES);

    dim3 grid(NTILES, BB);     // 128 blocks, one wave
    ncuts_fused_kernel<<<grid, 512, SMEM_BYTES>>>(seg, pad, wgt, sw, out);
}